// round 7
// baseline (speedup 1.0000x reference)
#include <cuda_runtime.h>
#include <cuda_bf16.h>
#include <math.h>

// Problem constants (fixed by the dataset)
#define NN   100000
#define EE   1600000
#define F_IN 128
#define HID  256
#define NC   64

// ---------------------------------------------------------------------------
// Scratch (static __device__ arrays — no allocation allowed)
// ---------------------------------------------------------------------------
__device__ float g_deg[NN];
__device__ float g_dinv[NN];
__device__ int   g_wptr[NN];        // counts, then write cursors
__device__ int   g_rowptr[NN + 1];
__device__ int   g_csrc[EE];
__device__ float g_cnorm[EE];
__device__ __align__(16) float g_bufA[(size_t)NN * HID];
__device__ __align__(16) float g_bufB[(size_t)NN * HID];

// ---------------------------------------------------------------------------
// Preprocessing kernels
// ---------------------------------------------------------------------------
__global__ void k_init()
{
    int i = blockIdx.x * blockDim.x + threadIdx.x;
    if (i < NN) {
        g_deg[i]  = 1.0f;   // self-loop weight
        g_wptr[i] = 0;
    }
}

__global__ void k_deg_count(const int* __restrict__ dst, const float* __restrict__ w)
{
    int e = blockIdx.x * blockDim.x + threadIdx.x;
    if (e < EE) {
        int d = dst[e];
        atomicAdd(&g_deg[d], w[e]);
        atomicAdd(&g_wptr[d], 1);
    }
}

__global__ void k_dinv()
{
    int i = blockIdx.x * blockDim.x + threadIdx.x;
    if (i < NN) g_dinv[i] = rsqrtf(g_deg[i]);   // deg >= 1 always (self-loop)
}

// Single-block exclusive scan of counts -> row_ptr; also resets g_wptr to
// the start offsets so the fill kernel can atomically bump them.
__global__ void k_scan()
{
    constexpr int T = 1024;
    constexpr int CHUNK = (NN + T - 1) / T;     // 98
    __shared__ int sh[T];
    int t = threadIdx.x;
    int beg = t * CHUNK;
    int end = beg + CHUNK; if (end > NN) end = NN;

    int s = 0;
    for (int i = beg; i < end && i < NN; i++) s += g_wptr[i];
    sh[t] = s;
    __syncthreads();

    // Hillis-Steele inclusive scan
    for (int off = 1; off < T; off <<= 1) {
        int v = (t >= off) ? sh[t - off] : 0;
        __syncthreads();
        sh[t] += v;
        __syncthreads();
    }

    int run = sh[t] - s;    // exclusive prefix for this chunk
    for (int i = beg; i < end && i < NN; i++) {
        int c = g_wptr[i];
        g_rowptr[i] = run;
        g_wptr[i]   = run;  // write cursor
        run += c;
    }
    if (t == T - 1) g_rowptr[NN] = sh[T - 1];
}

__global__ void k_fill(const int* __restrict__ src, const int* __restrict__ dst,
                       const float* __restrict__ w)
{
    int e = blockIdx.x * blockDim.x + threadIdx.x;
    if (e < EE) {
        int s = src[e], d = dst[e];
        float nm = g_dinv[s] * w[e] * g_dinv[d];
        int slot = atomicAdd(&g_wptr[d], 1);
        g_csrc[slot]  = s;
        g_cnorm[slot] = nm;
    }
}

// ---------------------------------------------------------------------------
// Register-tiled SGEMM:  C[M,Ncols] = A[M,K] @ B[K,Ncols]   (all row-major)
// ---------------------------------------------------------------------------
template <int BM, int BN, int BK, int TM, int TN>
__global__ void __launch_bounds__(256)
sgemm_k(int M, int Ncols, int K,
        const float* __restrict__ A, const float* __restrict__ B,
        float* __restrict__ C)
{
    constexpr int NT = (BM / TM) * (BN / TN);
    static_assert(NT == 256, "256 threads expected");

    __shared__ float As[BK][BM];   // A tile stored transposed
    __shared__ float Bs[BK][BN];

    const int tid  = threadIdx.x;
    const int brow = blockIdx.y;
    const int bcol = blockIdx.x;
    const int tcol = tid % (BN / TN);
    const int trow = tid / (BN / TN);
    const int rowBase = brow * BM;

    float acc[TM][TN] = {};
    float rM[TM], rN[TN];

    for (int k0 = 0; k0 < K; k0 += BK) {
        // load A tile (transposed into smem), zero-fill out-of-range rows
        #pragma unroll
        for (int i = tid; i < BM * BK / 4; i += NT) {
            int e4 = i * 4;
            int r  = e4 / BK, c = e4 % BK;
            float4 v = make_float4(0.f, 0.f, 0.f, 0.f);
            int gr = rowBase + r;
            if (gr < M)
                v = *reinterpret_cast<const float4*>(A + (size_t)gr * K + k0 + c);
            As[c + 0][r] = v.x; As[c + 1][r] = v.y;
            As[c + 2][r] = v.z; As[c + 3][r] = v.w;
        }
        // load B tile
        #pragma unroll
        for (int i = tid; i < BK * BN / 4; i += NT) {
            int e4 = i * 4;
            int r  = e4 / BN, c = e4 % BN;
            *reinterpret_cast<float4*>(&Bs[r][c]) =
                *reinterpret_cast<const float4*>(B + (size_t)(k0 + r) * Ncols + bcol * BN + c);
        }
        __syncthreads();

        #pragma unroll
        for (int k = 0; k < BK; k++) {
            #pragma unroll
            for (int m = 0; m < TM; m += 4)
                *reinterpret_cast<float4*>(&rM[m]) =
                    *reinterpret_cast<const float4*>(&As[k][trow * TM + m]);
            #pragma unroll
            for (int n = 0; n < TN; n += 4)
                *reinterpret_cast<float4*>(&rN[n]) =
                    *reinterpret_cast<const float4*>(&Bs[k][tcol * TN + n]);
            #pragma unroll
            for (int m = 0; m < TM; m++)
                #pragma unroll
                for (int n = 0; n < TN; n++)
                    acc[m][n] += rM[m] * rN[n];
        }
        __syncthreads();
    }

    #pragma unroll
    for (int m = 0; m < TM; m++) {
        int gr = rowBase + trow * TM + m;
        if (gr >= M) continue;
        #pragma unroll
        for (int n = 0; n < TN; n += 4) {
            float4 v = make_float4(acc[m][n], acc[m][n + 1], acc[m][n + 2], acc[m][n + 3]);
            *reinterpret_cast<float4*>(C + (size_t)gr * Ncols + bcol * BN + tcol * TN + n) = v;
        }
    }
}

// ---------------------------------------------------------------------------
// Gather aggregation:  out[i] = act( sum_{e in CSR[i]} norm_e * t[src_e]
//                                    + dinv[i]^2 * t[i] + bias )
// ---------------------------------------------------------------------------
template <int D, bool RELU>
__global__ void agg_k(const float* __restrict__ t, float* __restrict__ out,
                      const float* __restrict__ bias, int n)
{
    constexpr int G = 256 / D;          // nodes per block
    const int lane = threadIdx.x % D;
    const int sub  = threadIdx.x / D;
    const float b  = bias[lane];

    for (int base = blockIdx.x * G; base < n; base += gridDim.x * G) {
        int node = base + sub;
        if (node >= n) continue;
        float di   = g_dinv[node];
        float acc0 = di * di * __ldg(t + (size_t)node * D + lane);
        float acc1 = 0.f;
        int e   = g_rowptr[node];
        int end = g_rowptr[node + 1];
        for (; e + 1 < end; e += 2) {
            int   s0 = g_csrc[e],   s1 = g_csrc[e + 1];
            float w0 = g_cnorm[e],  w1 = g_cnorm[e + 1];
            acc0 += w0 * __ldg(t + (size_t)s0 * D + lane);
            acc1 += w1 * __ldg(t + (size_t)s1 * D + lane);
        }
        if (e < end)
            acc0 += g_cnorm[e] * __ldg(t + (size_t)g_csrc[e] * D + lane);
        float r = acc0 + acc1 + b;
        if (RELU) r = fmaxf(r, 0.f);
        out[(size_t)node * D + lane] = r;
    }
}

// ---------------------------------------------------------------------------
// Launch
// ---------------------------------------------------------------------------
extern "C" void kernel_launch(void* const* d_in, const int* in_sizes, int n_in,
                              void* d_out, int out_size)
{
    const float* x  = (const float*)d_in[0];
    const int*   ei = (const int*)  d_in[1];
    const float* ew = (const float*)d_in[2];
    const float* W0 = (const float*)d_in[3];
    const float* b0 = (const float*)d_in[4];
    const float* W1 = (const float*)d_in[5];
    const float* b1 = (const float*)d_in[6];
    const float* W2 = (const float*)d_in[7];
    const float* b2 = (const float*)d_in[8];
    float* out = (float*)d_out;

    const int* src = ei;        // edge_index[0]
    const int* dst = ei + EE;   // edge_index[1]

    float* bufA = nullptr;
    float* bufB = nullptr;
    cudaGetSymbolAddress((void**)&bufA, g_bufA);
    cudaGetSymbolAddress((void**)&bufB, g_bufB);

    const int TB = 256;
    const int gN = (NN + TB - 1) / TB;
    const int gE = (EE + TB - 1) / TB;

    // ---- GCN normalization + CSR build ----
    k_init<<<gN, TB>>>();
    k_deg_count<<<gE, TB>>>(dst, ew);
    k_dinv<<<gN, TB>>>();
    k_scan<<<1, 1024>>>();
    k_fill<<<gE, TB>>>(src, dst, ew);

    const int gridM = (NN + 127) / 128;  // 782

    // ---- Layer 0: t = x @ W0 ; h = relu(agg(t) + b0) ----
    sgemm_k<128, 128, 8, 8, 8><<<dim3(HID / 128, gridM), 256>>>(NN, HID, F_IN, x, W0, bufA);
    agg_k<HID, true><<<NN, 256>>>(bufA, bufB, b0, NN);

    // ---- Layer 1 ----
    sgemm_k<128, 128, 8, 8, 8><<<dim3(HID / 128, gridM), 256>>>(NN, HID, HID, bufB, W1, bufA);
    agg_k<HID, true><<<NN, 256>>>(bufA, bufB, b1, NN);

    // ---- Layer 2 (no relu), write straight to d_out ----
    sgemm_k<128, 64, 8, 8, 4><<<dim3(NC / 64, gridM), 256>>>(NN, NC, HID, bufB, W2, bufA);
    agg_k<NC, false><<<(NN + 3) / 4, 256>>>(bufA, out, b2, NN);
}

// round 9
// speedup vs baseline: 2.0449x; 2.0449x over previous
#include <cuda_runtime.h>
#include <cuda_bf16.h>
#include <cstdint>
#include <math.h>

// Problem constants (fixed by the dataset)
#define NN   100000
#define EE   1600000
#define F_IN 128
#define HID  256
#define NC   64
#define NBLK ((NN + 255) / 256)   // 391

// ---------------------------------------------------------------------------
// Scratch (static __device__ arrays — no allocation allowed)
// ---------------------------------------------------------------------------
__device__ float g_deg[NN];
__device__ float g_dinv[NN];
__device__ int   g_wptr[NN];
__device__ int   g_rowptr[NN + 1];
__device__ int   g_blksum[NBLK];
__device__ int   g_blkoff[NBLK];
__device__ int   g_csrc[EE];
__device__ float g_cnorm[EE];
__device__ __align__(16) float         g_bufA[(size_t)NN * HID];   // GEMM fp32 out
__device__ __align__(16) __nv_bfloat16 g_hi[(size_t)NN * HID];     // activations hi
__device__ __align__(16) __nv_bfloat16 g_lo[(size_t)NN * HID];     // activations lo
__device__ __align__(16) __nv_bfloat16 g_xhi[(size_t)NN * F_IN];
__device__ __align__(16) __nv_bfloat16 g_xlo[(size_t)NN * F_IN];
__device__ __align__(16) __nv_bfloat16 g_w0hi[HID * F_IN], g_w0lo[HID * F_IN];
__device__ __align__(16) __nv_bfloat16 g_w1hi[HID * HID],  g_w1lo[HID * HID];
__device__ __align__(16) __nv_bfloat16 g_w2hi[NC * HID],   g_w2lo[NC * HID];

// ---------------------------------------------------------------------------
// Warp MMA helpers (portable sm_80+ HMMA; works on generic sm_103 target)
// ---------------------------------------------------------------------------
__device__ __forceinline__ uint32_t smem_u32(const void* p) {
    uint32_t a;
    asm("{ .reg .u64 t; cvta.to.shared.u64 t, %1; cvt.u32.u64 %0, t; }"
        : "=r"(a) : "l"(p));
    return a;
}

#define LDSM4(r, addr) \
    asm volatile("ldmatrix.sync.aligned.m8n8.x4.shared.b16 {%0,%1,%2,%3}, [%4];" \
        : "=r"((r)[0]), "=r"((r)[1]), "=r"((r)[2]), "=r"((r)[3]) : "r"(addr))

#define MMA_BF16(c, a, b0, b1) \
    asm volatile("mma.sync.aligned.m16n8k16.row.col.f32.bf16.bf16.f32 " \
        "{%0,%1,%2,%3}, {%4,%5,%6,%7}, {%8,%9}, {%0,%1,%2,%3};" \
        : "+f"((c)[0]), "+f"((c)[1]), "+f"((c)[2]), "+f"((c)[3]) \
        : "r"((a)[0]), "r"((a)[1]), "r"((a)[2]), "r"((a)[3]), "r"(b0), "r"(b1))

// ---------------------------------------------------------------------------
// Preprocessing kernels
// ---------------------------------------------------------------------------
__global__ void k_init()
{
    int i = blockIdx.x * blockDim.x + threadIdx.x;
    if (i < NN) { g_deg[i] = 1.0f; g_wptr[i] = 0; }
}

__global__ void k_deg_count(const int* __restrict__ dst, const float* __restrict__ w)
{
    int e = blockIdx.x * blockDim.x + threadIdx.x;
    if (e < EE) {
        int d = dst[e];
        atomicAdd(&g_deg[d], w[e]);
        atomicAdd(&g_wptr[d], 1);
    }
}

__global__ void k_dinv()
{
    int i = blockIdx.x * blockDim.x + threadIdx.x;
    if (i < NN) g_dinv[i] = rsqrtf(g_deg[i]);
}

__global__ void k_blocksum()
{
    __shared__ int sh[256];
    int i = blockIdx.x * 256 + threadIdx.x;
    sh[threadIdx.x] = (i < NN) ? g_wptr[i] : 0;
    __syncthreads();
    for (int o = 128; o > 0; o >>= 1) {
        if (threadIdx.x < o) sh[threadIdx.x] += sh[threadIdx.x + o];
        __syncthreads();
    }
    if (threadIdx.x == 0) g_blksum[blockIdx.x] = sh[0];
}

__global__ void k_scanblk()
{
    __shared__ int sh[512];
    int t = threadIdx.x;
    int v = (t < NBLK) ? g_blksum[t] : 0;
    sh[t] = v;
    __syncthreads();
    for (int o = 1; o < 512; o <<= 1) {
        int a = (t >= o) ? sh[t - o] : 0;
        __syncthreads();
        sh[t] += a;
        __syncthreads();
    }
    if (t < NBLK) g_blkoff[t] = sh[t] - v;   // exclusive
}

__global__ void k_rowptr()
{
    __shared__ int sh[256];
    int i = blockIdx.x * 256 + threadIdx.x;
    int v = (i < NN) ? g_wptr[i] : 0;
    sh[threadIdx.x] = v;
    __syncthreads();
    for (int o = 1; o < 256; o <<= 1) {
        int a = (threadIdx.x >= o) ? sh[threadIdx.x - o] : 0;
        __syncthreads();
        sh[threadIdx.x] += a;
        __syncthreads();
    }
    if (i < NN) {
        int off = g_blkoff[blockIdx.x] + sh[threadIdx.x] - v;
        g_rowptr[i] = off;
        g_wptr[i]   = off;   // write cursor for fill
    }
    if (i == NN - 1) g_rowptr[NN] = EE;
}

__global__ void k_fill(const int* __restrict__ src, const int* __restrict__ dst,
                       const float* __restrict__ w)
{
    int e = blockIdx.x * blockDim.x + threadIdx.x;
    if (e < EE) {
        int s = src[e], d = dst[e];
        float nm = g_dinv[s] * w[e] * g_dinv[d];
        int slot = atomicAdd(&g_wptr[d], 1);
        g_csrc[slot]  = s;
        g_cnorm[slot] = nm;
    }
}

// ---------------------------------------------------------------------------
// fp32 -> (hi, lo) bf16 split
// ---------------------------------------------------------------------------
__global__ void k_split(const float* __restrict__ in,
                        __nv_bfloat16* __restrict__ hi,
                        __nv_bfloat16* __restrict__ lo, int n)
{
    int i = blockIdx.x * blockDim.x + threadIdx.x;
    if (i < n) {
        float v = in[i];
        __nv_bfloat16 h = __float2bfloat16(v);
        hi[i] = h;
        lo[i] = __float2bfloat16(v - __bfloat162float(h));
    }
}

// W[K,N] row-major -> Wt[N,K] K-major, split hi/lo
__global__ void k_wsplit(const float* __restrict__ W,
                         __nv_bfloat16* __restrict__ thi,
                         __nv_bfloat16* __restrict__ tlo, int K, int Ncols)
{
    int i = blockIdx.x * blockDim.x + threadIdx.x;   // i = n*K + k
    if (i < K * Ncols) {
        int n = i / K, k = i % K;
        float v = W[k * Ncols + n];
        __nv_bfloat16 h = __float2bfloat16(v);
        thi[i] = h;
        tlo[i] = __float2bfloat16(v - __bfloat162float(h));
    }
}

// ---------------------------------------------------------------------------
// HMMA split-bf16 GEMM:  C[M, ldc] = A[M, KT] @ Bt[Ncols, KT]^T
//   A, Bt stored hi/lo bf16, K-major.  3 terms: Ah*Bh + Ah*Bl + Al*Bh.
//   BM=128, BK=32, 256 threads: warp grid 4(m) x 2(n), warp tile 32 x (BN/2).
// ---------------------------------------------------------------------------
template <int BN>
__global__ void __launch_bounds__(256)
gemm_mma(int M, int KT,
         const __nv_bfloat16* __restrict__ Ahi, const __nv_bfloat16* __restrict__ Alo,
         const __nv_bfloat16* __restrict__ Bhi, const __nv_bfloat16* __restrict__ Blo,
         float* __restrict__ C, int ldc)
{
    constexpr int BK = 32;
    constexpr int SB = BK * 2 + 16;     // 80 B padded row (conflict-free ldmatrix)
    constexpr int WN = BN / 2;          // warp n-extent
    constexpr int NF = WN / 8;          // 8-wide n fragments per warp

    __shared__ __align__(16) char sm[(256 + 2 * BN) * SB];
    char* sAhi = sm;
    char* sAlo = sm + 128 * SB;
    char* sBhi = sm + 256 * SB;
    char* sBlo = sm + (256 + BN) * SB;

    const int tid  = threadIdx.x;
    const int lane = tid & 31, wid = tid >> 5;
    const int wm = wid & 3;             // 0..3
    const int wn = wid >> 2;            // 0..1
    const int rowBase = blockIdx.y * 128;
    const int colBase = blockIdx.x * BN;

    float c[2][NF][4];
    #pragma unroll
    for (int mi = 0; mi < 2; mi++)
        #pragma unroll
        for (int nf = 0; nf < NF; nf++)
            #pragma unroll
            for (int j = 0; j < 4; j++) c[mi][nf][j] = 0.f;

    // ldmatrix base addresses (per-thread row within warp tile)
    const uint32_t aHiB = smem_u32(sAhi) + (wm * 32 + (lane & 15)) * SB + (lane >> 4) * 16;
    const uint32_t aLoB = smem_u32(sAlo) + (wm * 32 + (lane & 15)) * SB + (lane >> 4) * 16;
    const uint32_t bHiB = smem_u32(sBhi) + (wn * WN + (lane & 15)) * SB + (lane >> 4) * 16;
    const uint32_t bLoB = smem_u32(sBlo) + (wn * WN + (lane & 15)) * SB + (lane >> 4) * 16;

    const int nchunk = KT >> 5;
    for (int ch = 0; ch < nchunk; ch++) {
        const int k0 = ch * BK;
        // ---- load A tile (hi+lo), zero-fill rows >= M ----
        #pragma unroll
        for (int i = tid; i < 128 * 4; i += 256) {
            int row = i >> 2, cc = i & 3;
            int gr = rowBase + row;
            float4 vh = make_float4(0.f, 0.f, 0.f, 0.f), vl = vh;
            if (gr < M) {
                const size_t go = (size_t)gr * KT + k0 + cc * 8;
                vh = *(const float4*)(Ahi + go);
                vl = *(const float4*)(Alo + go);
            }
            *(float4*)(sAhi + row * SB + cc * 16) = vh;
            *(float4*)(sAlo + row * SB + cc * 16) = vl;
        }
        // ---- load B tile (hi+lo) ----
        #pragma unroll
        for (int i = tid; i < BN * 4; i += 256) {
            int row = i >> 2, cc = i & 3;
            const size_t go = (size_t)(colBase + row) * KT + k0 + cc * 8;
            *(float4*)(sBhi + row * SB + cc * 16) = *(const float4*)(Bhi + go);
            *(float4*)(sBlo + row * SB + cc * 16) = *(const float4*)(Blo + go);
        }
        __syncthreads();

        #pragma unroll
        for (int ks = 0; ks < 2; ks++) {
            const int kb = ks * 32;     // 16 bf16 = 32 B per k-step
            uint32_t ah[2][4], al[2][4];
            #pragma unroll
            for (int mi = 0; mi < 2; mi++) {
                LDSM4(ah[mi], aHiB + mi * (16 * SB) + kb);
                LDSM4(al[mi], aLoB + mi * (16 * SB) + kb);
            }
            uint32_t bh[NF / 2][4], bl[NF / 2][4];
            #pragma unroll
            for (int p = 0; p < NF / 2; p++) {
                LDSM4(bh[p], bHiB + p * (16 * SB) + kb);
                LDSM4(bl[p], bLoB + p * (16 * SB) + kb);
            }
            #pragma unroll
            for (int mi = 0; mi < 2; mi++)
                #pragma unroll
                for (int nf = 0; nf < NF; nf++) {
                    const int p = nf >> 1, s = nf & 1;
                    MMA_BF16(c[mi][nf], ah[mi], bh[p][s], bh[p][s + 2]);
                    MMA_BF16(c[mi][nf], ah[mi], bl[p][s], bl[p][s + 2]);
                    MMA_BF16(c[mi][nf], al[mi], bh[p][s], bh[p][s + 2]);
                }
        }
        __syncthreads();
    }

    // ---- epilogue: fragment -> fp32 C ----
    #pragma unroll
    for (int mi = 0; mi < 2; mi++) {
        const int r0 = rowBase + wm * 32 + mi * 16 + (lane >> 2);
        #pragma unroll
        for (int nf = 0; nf < NF; nf++) {
            const int col = colBase + wn * WN + nf * 8 + (lane & 3) * 2;
            if (r0 < M)
                *(float2*)(C + (size_t)r0 * ldc + col) = make_float2(c[mi][nf][0], c[mi][nf][1]);
            if (r0 + 8 < M)
                *(float2*)(C + (size_t)(r0 + 8) * ldc + col) = make_float2(c[mi][nf][2], c[mi][nf][3]);
        }
    }
}

// ---------------------------------------------------------------------------
// Gather aggregation (float4 lanes):
//   r = sum_e norm_e * t[src_e] + dinv[i]^2 * t[i] + bias ; relu
//   EMIT: write bf16 hi/lo split (feeds next GEMM); else fp32.
// ---------------------------------------------------------------------------
template <int D, bool RELU, bool EMIT>
__global__ void agg_k(const float* __restrict__ t, float* __restrict__ outf,
                      __nv_bfloat16* __restrict__ ohi, __nv_bfloat16* __restrict__ olo,
                      const float* __restrict__ bias, int n)
{
    constexpr int L = D / 4;        // lanes per node
    constexpr int G = 256 / L;      // nodes per block
    const int lane = threadIdx.x % L;
    const int sub  = threadIdx.x / L;
    const int node = blockIdx.x * G + sub;
    if (node >= n) return;

    float4 b = ((const float4*)bias)[lane];
    float di = g_dinv[node];
    float s  = di * di;
    float4 self = __ldg((const float4*)(t + (size_t)node * D) + lane);
    float4 a0 = make_float4(s * self.x + b.x, s * self.y + b.y,
                            s * self.z + b.z, s * self.w + b.w);
    float4 a1 = make_float4(0.f, 0.f, 0.f, 0.f);

    int e   = g_rowptr[node];
    int end = g_rowptr[node + 1];
    for (; e + 1 < end; e += 2) {
        int   s0 = g_csrc[e],  s1 = g_csrc[e + 1];
        float w0 = g_cnorm[e], w1 = g_cnorm[e + 1];
        float4 v0 = __ldg((const float4*)(t + (size_t)s0 * D) + lane);
        float4 v1 = __ldg((const float4*)(t + (size_t)s1 * D) + lane);
        a0.x += w0 * v0.x; a0.y += w0 * v0.y; a0.z += w0 * v0.z; a0.w += w0 * v0.w;
        a1.x += w1 * v1.x; a1.y += w1 * v1.y; a1.z += w1 * v1.z; a1.w += w1 * v1.w;
    }
    if (e < end) {
        float w0 = g_cnorm[e];
        float4 v0 = __ldg((const float4*)(t + (size_t)g_csrc[e] * D) + lane);
        a0.x += w0 * v0.x; a0.y += w0 * v0.y; a0.z += w0 * v0.z; a0.w += w0 * v0.w;
    }
    float4 r = make_float4(a0.x + a1.x, a0.y + a1.y, a0.z + a1.z, a0.w + a1.w);
    if (RELU) {
        r.x = fmaxf(r.x, 0.f); r.y = fmaxf(r.y, 0.f);
        r.z = fmaxf(r.z, 0.f); r.w = fmaxf(r.w, 0.f);
    }
    if (EMIT) {
        size_t o = (size_t)node * D + lane * 4;
        __nv_bfloat16 h0 = __float2bfloat16(r.x), h1 = __float2bfloat16(r.y);
        __nv_bfloat16 h2 = __float2bfloat16(r.z), h3 = __float2bfloat16(r.w);
        ((__nv_bfloat162*)(ohi + o))[0] = __nv_bfloat162(h0, h1);
        ((__nv_bfloat162*)(ohi + o))[1] = __nv_bfloat162(h2, h3);
        __nv_bfloat16 l0 = __float2bfloat16(r.x - __bfloat162float(h0));
        __nv_bfloat16 l1 = __float2bfloat16(r.y - __bfloat162float(h1));
        __nv_bfloat16 l2 = __float2bfloat16(r.z - __bfloat162float(h2));
        __nv_bfloat16 l3 = __float2bfloat16(r.w - __bfloat162float(h3));
        ((__nv_bfloat162*)(olo + o))[0] = __nv_bfloat162(l0, l1);
        ((__nv_bfloat162*)(olo + o))[1] = __nv_bfloat162(l2, l3);
    } else {
        ((float4*)(outf + (size_t)node * D))[lane] = r;
    }
}

// ---------------------------------------------------------------------------
// Launch
// ---------------------------------------------------------------------------
extern "C" void kernel_launch(void* const* d_in, const int* in_sizes, int n_in,
                              void* d_out, int out_size)
{
    const float* x  = (const float*)d_in[0];
    const int*   ei = (const int*)  d_in[1];
    const float* ew = (const float*)d_in[2];
    const float* W0 = (const float*)d_in[3];
    const float* b0 = (const float*)d_in[4];
    const float* W1 = (const float*)d_in[5];
    const float* b1 = (const float*)d_in[6];
    const float* W2 = (const float*)d_in[7];
    const float* b2 = (const float*)d_in[8];
    float* out = (float*)d_out;

    const int* src = ei;
    const int* dst = ei + EE;

    float *bufA;
    __nv_bfloat16 *hi, *lo, *xhi, *xlo, *w0h, *w0l, *w1h, *w1l, *w2h, *w2l;
    cudaGetSymbolAddress((void**)&bufA, g_bufA);
    cudaGetSymbolAddress((void**)&hi,  g_hi);
    cudaGetSymbolAddress((void**)&lo,  g_lo);
    cudaGetSymbolAddress((void**)&xhi, g_xhi);
    cudaGetSymbolAddress((void**)&xlo, g_xlo);
    cudaGetSymbolAddress((void**)&w0h, g_w0hi); cudaGetSymbolAddress((void**)&w0l, g_w0lo);
    cudaGetSymbolAddress((void**)&w1h, g_w1hi); cudaGetSymbolAddress((void**)&w1l, g_w1lo);
    cudaGetSymbolAddress((void**)&w2h, g_w2hi); cudaGetSymbolAddress((void**)&w2l, g_w2lo);

    const int TB = 256;
    const int gN = (NN + TB - 1) / TB;
    const int gE = (EE + TB - 1) / TB;

    // ---- normalization + coalesced CSR build ----
    k_init<<<gN, TB>>>();
    k_deg_count<<<gE, TB>>>(dst, ew);
    k_dinv<<<gN, TB>>>();
    k_blocksum<<<NBLK, 256>>>();
    k_scanblk<<<1, 512>>>();
    k_rowptr<<<NBLK, 256>>>();
    k_fill<<<gE, TB>>>(src, dst, ew);

    // ---- operand prep: split x, transpose+split weights ----
    k_split<<<(NN * F_IN + 255) / 256, 256>>>(x, xhi, xlo, NN * F_IN);
    k_wsplit<<<(F_IN * HID + 255) / 256, 256>>>(W0, w0h, w0l, F_IN, HID);
    k_wsplit<<<(HID * HID + 255) / 256, 256>>>(W1, w1h, w1l, HID, HID);
    k_wsplit<<<(HID * NC + 255) / 256, 256>>>(W2, w2h, w2l, HID, NC);

    const int gridM = (NN + 127) / 128;   // 782

    // ---- Layer 0: T = X @ W0 ; h = relu(agg(T) + b0) -> hi/lo ----
    gemm_mma<128><<<dim3(HID / 128, gridM), 256>>>(NN, F_IN, xhi, xlo, w0h, w0l, bufA, HID);
    agg_k<HID, true, true><<<(NN + 3) / 4, 256>>>(bufA, nullptr, hi, lo, b0, NN);

    // ---- Layer 1 ----
    gemm_mma<128><<<dim3(HID / 128, gridM), 256>>>(NN, HID, hi, lo, w1h, w1l, bufA, HID);
    agg_k<HID, true, true><<<(NN + 3) / 4, 256>>>(bufA, nullptr, hi, lo, b1, NN);

    // ---- Layer 2 (no relu), fp32 straight to d_out ----
    gemm_mma<64><<<dim3(NC / 64, gridM), 256>>>(NN, HID, hi, lo, w2h, w2l, bufA, NC);
    agg_k<NC, false, false><<<(NN + 15) / 16, 256>>>(bufA, out, nullptr, nullptr, b2, NN);
}

// round 10
// speedup vs baseline: 2.7115x; 1.3260x over previous
#include <cuda_runtime.h>
#include <cuda_bf16.h>
#include <cstdint>
#include <math.h>

// Problem constants (fixed by the dataset)
#define NN   100000
#define EE   1600000
#define F_IN 128
#define HID  256
#define NC   64
#define NBLK ((NN + 255) / 256)   // 391

// ---------------------------------------------------------------------------
// Scratch (static __device__ arrays — no allocation allowed)
// ---------------------------------------------------------------------------
__device__ float g_deg[NN];
__device__ float g_dinv[NN];
__device__ int   g_wptr[NN];
__device__ int   g_rowptr[NN + 1];
__device__ int   g_blksum[NBLK];
__device__ int   g_blkoff[NBLK];
__device__ int   g_csrc[EE];
__device__ float g_cnorm[EE];
__device__ __align__(16) float         g_bufA[(size_t)NN * HID];   // GEMM fp32 out
__device__ __align__(16) __nv_bfloat16 g_hi[(size_t)NN * HID];     // activations hi
__device__ __align__(16) __nv_bfloat16 g_lo[(size_t)NN * HID];     // activations lo
__device__ __align__(16) __nv_bfloat16 g_xhi[(size_t)NN * F_IN];   // agg(x) hi
__device__ __align__(16) __nv_bfloat16 g_xlo[(size_t)NN * F_IN];   // agg(x) lo
__device__ __align__(16) __nv_bfloat16 g_w0hi[HID * F_IN], g_w0lo[HID * F_IN];
__device__ __align__(16) __nv_bfloat16 g_w1hi[HID * HID],  g_w1lo[HID * HID];
__device__ __align__(16) __nv_bfloat16 g_w2hi[NC * HID],   g_w2lo[NC * HID];

// ---------------------------------------------------------------------------
// PTX helpers (portable sm_80+; works on generic sm_103 target)
// ---------------------------------------------------------------------------
__device__ __forceinline__ uint32_t smem_u32(const void* p) {
    uint32_t a;
    asm("{ .reg .u64 t; cvta.to.shared.u64 t, %1; cvt.u32.u64 %0, t; }"
        : "=r"(a) : "l"(p));
    return a;
}

#define LDSM4(r, addr) \
    asm volatile("ldmatrix.sync.aligned.m8n8.x4.shared.b16 {%0,%1,%2,%3}, [%4];" \
        : "=r"((r)[0]), "=r"((r)[1]), "=r"((r)[2]), "=r"((r)[3]) : "r"(addr))

#define MMA_BF16(c, a, b0, b1) \
    asm volatile("mma.sync.aligned.m16n8k16.row.col.f32.bf16.bf16.f32 " \
        "{%0,%1,%2,%3}, {%4,%5,%6,%7}, {%8,%9}, {%0,%1,%2,%3};" \
        : "+f"((c)[0]), "+f"((c)[1]), "+f"((c)[2]), "+f"((c)[3]) \
        : "r"((a)[0]), "r"((a)[1]), "r"((a)[2]), "r"((a)[3]), "r"(b0), "r"(b1))

#define CP16(dst, src, sz) \
    asm volatile("cp.async.cg.shared.global [%0], [%1], 16, %2;" \
        :: "r"(dst), "l"(src), "r"(sz) : "memory")
#define CP_COMMIT() asm volatile("cp.async.commit_group;" ::: "memory")
template <int N>
__device__ __forceinline__ void cp_wait() {
    asm volatile("cp.async.wait_group %0;" :: "n"(N) : "memory");
}

// ---------------------------------------------------------------------------
// Preprocessing kernels
// ---------------------------------------------------------------------------
__global__ void k_init()
{
    int i = blockIdx.x * blockDim.x + threadIdx.x;
    if (i < NN) { g_deg[i] = 1.0f; g_wptr[i] = 0; }
}

__global__ void k_deg_count(const int* __restrict__ dst, const float* __restrict__ w)
{
    int e = blockIdx.x * blockDim.x + threadIdx.x;
    if (e < EE) {
        int d = dst[e];
        atomicAdd(&g_deg[d], w[e]);
        atomicAdd(&g_wptr[d], 1);
    }
}

__global__ void k_dinv()
{
    int i = blockIdx.x * blockDim.x + threadIdx.x;
    if (i < NN) g_dinv[i] = rsqrtf(g_deg[i]);
}

__global__ void k_blocksum()
{
    __shared__ int sh[256];
    int i = blockIdx.x * 256 + threadIdx.x;
    sh[threadIdx.x] = (i < NN) ? g_wptr[i] : 0;
    __syncthreads();
    for (int o = 128; o > 0; o >>= 1) {
        if (threadIdx.x < o) sh[threadIdx.x] += sh[threadIdx.x + o];
        __syncthreads();
    }
    if (threadIdx.x == 0) g_blksum[blockIdx.x] = sh[0];
}

__global__ void k_scanblk()
{
    __shared__ int sh[512];
    int t = threadIdx.x;
    int v = (t < NBLK) ? g_blksum[t] : 0;
    sh[t] = v;
    __syncthreads();
    for (int o = 1; o < 512; o <<= 1) {
        int a = (t >= o) ? sh[t - o] : 0;
        __syncthreads();
        sh[t] += a;
        __syncthreads();
    }
    if (t < NBLK) g_blkoff[t] = sh[t] - v;   // exclusive
}

__global__ void k_rowptr()
{
    __shared__ int sh[256];
    int i = blockIdx.x * 256 + threadIdx.x;
    int v = (i < NN) ? g_wptr[i] : 0;
    sh[threadIdx.x] = v;
    __syncthreads();
    for (int o = 1; o < 256; o <<= 1) {
        int a = (threadIdx.x >= o) ? sh[threadIdx.x - o] : 0;
        __syncthreads();
        sh[threadIdx.x] += a;
        __syncthreads();
    }
    if (i < NN) {
        int off = g_blkoff[blockIdx.x] + sh[threadIdx.x] - v;
        g_rowptr[i] = off;
        g_wptr[i]   = off;   // write cursor for fill
    }
    if (i == NN - 1) g_rowptr[NN] = EE;
}

__global__ void k_fill(const int* __restrict__ src, const int* __restrict__ dst,
                       const float* __restrict__ w)
{
    int e = blockIdx.x * blockDim.x + threadIdx.x;
    if (e < EE) {
        int s = src[e], d = dst[e];
        float nm = g_dinv[s] * w[e] * g_dinv[d];
        int slot = atomicAdd(&g_wptr[d], 1);
        g_csrc[slot]  = s;
        g_cnorm[slot] = nm;
    }
}

// W[K,N] row-major -> Wt[N,K] K-major, split hi/lo
__global__ void k_wsplit(const float* __restrict__ W,
                         __nv_bfloat16* __restrict__ thi,
                         __nv_bfloat16* __restrict__ tlo, int K, int Ncols)
{
    int i = blockIdx.x * blockDim.x + threadIdx.x;   // i = n*K + k
    if (i < K * Ncols) {
        int n = i / K, k = i % K;
        float v = W[k * Ncols + n];
        __nv_bfloat16 h = __float2bfloat16(v);
        thi[i] = h;
        tlo[i] = __float2bfloat16(v - __bfloat162float(h));
    }
}

// ---------------------------------------------------------------------------
// HMMA split-bf16 GEMM, cp.async double-buffered.
//   C[M, ldc] = A[M, KT] @ Bt[Ncols, KT]^T ; 3 terms Ah*Bh + Ah*Bl + Al*Bh.
//   BM=128, BN=64, BK=32, 256 threads (warps 4m x 2n, warp tile 32x32).
//   Smem: 2 stages x 24576 B, 64 B rows with XOR-16B swizzle (cp.async-aligned,
//   ldmatrix conflict-free). EPI=0: fp32 store. EPI=1: bias+relu+hi/lo bf16.
// ---------------------------------------------------------------------------
template <int EPI>
__global__ void __launch_bounds__(256)
gemm_mma(int M, int KT,
         const __nv_bfloat16* __restrict__ Ahi, const __nv_bfloat16* __restrict__ Alo,
         const __nv_bfloat16* __restrict__ Bhi, const __nv_bfloat16* __restrict__ Blo,
         float* __restrict__ Cf,
         __nv_bfloat16* __restrict__ Chi, __nv_bfloat16* __restrict__ Clo,
         const float* __restrict__ bias, int ldc)
{
    constexpr int STG = 24576;          // (128*2 + 64*2) rows * 64 B
    constexpr int OFF_AH = 0, OFF_AL = 8192, OFF_BH = 16384, OFF_BL = 20480;

    __shared__ __align__(16) char sm[2 * STG];
    const uint32_t smb = smem_u32(sm);

    const int tid  = threadIdx.x;
    const int lane = tid & 31, wid = tid >> 5;
    const int wm = wid & 3;             // 0..3  (m)
    const int wn = wid >> 2;            // 0..1  (n)
    const int rowBase = blockIdx.y * 128;
    const int colBase = blockIdx.x * 64;

    float c[2][4][4];
    #pragma unroll
    for (int mi = 0; mi < 2; mi++)
        #pragma unroll
        for (int nf = 0; nf < 4; nf++)
            #pragma unroll
            for (int j = 0; j < 4; j++) c[mi][nf][j] = 0.f;

    // ldmatrix per-lane rows + swizzle keys
    const int lane15 = lane & 15;
    int  rA[2], rB[2];
    rA[0] = wm * 32 + lane15;  rA[1] = rA[0] + 16;
    rB[0] = wn * 32 + lane15;  rB[1] = rB[0] + 16;
    const int swA0 = (rA[0] >> 1) & 3, swA1 = (rA[1] >> 1) & 3;
    const int swB0 = (rB[0] >> 1) & 3, swB1 = (rB[1] >> 1) & 3;
    const int ccB  = lane >> 4;

    const int nchunk = KT >> 5;

    // ---- tile loader (cp.async) ----
    auto ld_tiles = [&](int st, int ch) {
        const uint32_t sb = smb + st * STG;
        const int k0 = ch * 32;
        #pragma unroll
        for (int i = tid; i < 512; i += 256) {      // A: 128 rows x 4 chunks
            int row = i >> 2, cc = i & 3;
            int gr  = rowBase + row;
            uint32_t sz = (gr < M) ? 16u : 0u;
            int gra = (gr < M) ? gr : (M - 1);
            size_t go = (size_t)gra * KT + k0 + cc * 8;
            uint32_t d = row * 64 + (((cc ^ ((row >> 1) & 3))) << 4);
            CP16(sb + OFF_AH + d, (const char*)(Ahi + go), sz);
            CP16(sb + OFF_AL + d, (const char*)(Alo + go), sz);
        }
        {                                            // B: 64 rows x 4 chunks
            int row = tid >> 2, cc = tid & 3;
            size_t go = (size_t)(colBase + row) * KT + k0 + cc * 8;
            uint32_t d = row * 64 + (((cc ^ ((row >> 1) & 3))) << 4);
            CP16(sb + OFF_BH + d, (const char*)(Bhi + go), 16u);
            CP16(sb + OFF_BL + d, (const char*)(Blo + go), 16u);
        }
    };

    ld_tiles(0, 0);
    CP_COMMIT();

    for (int ch = 0; ch < nchunk; ch++) {
        if (ch + 1 < nchunk) { ld_tiles((ch + 1) & 1, ch + 1); CP_COMMIT(); }
        if (ch + 1 < nchunk) cp_wait<1>(); else cp_wait<0>();
        __syncthreads();

        const uint32_t sb = smb + (ch & 1) * STG;
        #pragma unroll
        for (int ks = 0; ks < 2; ks++) {
            const int cc = ccB + 2 * ks;
            uint32_t ah[2][4], al[2][4], bh[2][4], bl[2][4];
            LDSM4(ah[0], sb + OFF_AH + rA[0] * 64 + ((cc ^ swA0) << 4));
            LDSM4(ah[1], sb + OFF_AH + rA[1] * 64 + ((cc ^ swA1) << 4));
            LDSM4(al[0], sb + OFF_AL + rA[0] * 64 + ((cc ^ swA0) << 4));
            LDSM4(al[1], sb + OFF_AL + rA[1] * 64 + ((cc ^ swA1) << 4));
            LDSM4(bh[0], sb + OFF_BH + rB[0] * 64 + ((cc ^ swB0) << 4));
            LDSM4(bh[1], sb + OFF_BH + rB[1] * 64 + ((cc ^ swB1) << 4));
            LDSM4(bl[0], sb + OFF_BL + rB[0] * 64 + ((cc ^ swB0) << 4));
            LDSM4(bl[1], sb + OFF_BL + rB[1] * 64 + ((cc ^ swB1) << 4));
            #pragma unroll
            for (int mi = 0; mi < 2; mi++)
                #pragma unroll
                for (int nf = 0; nf < 4; nf++) {
                    const int p = nf >> 1, s = nf & 1;
                    MMA_BF16(c[mi][nf], ah[mi], bh[p][s], bh[p][s + 2]);
                    MMA_BF16(c[mi][nf], ah[mi], bl[p][s], bl[p][s + 2]);
                    MMA_BF16(c[mi][nf], al[mi], bh[p][s], bh[p][s + 2]);
                }
        }
        __syncthreads();
    }

    // ---- epilogue ----
    #pragma unroll
    for (int mi = 0; mi < 2; mi++) {
        const int r0 = rowBase + wm * 32 + mi * 16 + (lane >> 2);
        #pragma unroll
        for (int nf = 0; nf < 4; nf++) {
            const int col = colBase + wn * 32 + nf * 8 + (lane & 3) * 2;
            if (EPI == 0) {
                if (r0 < M)
                    *(float2*)(Cf + (size_t)r0 * ldc + col) =
                        make_float2(c[mi][nf][0], c[mi][nf][1]);
                if (r0 + 8 < M)
                    *(float2*)(Cf + (size_t)(r0 + 8) * ldc + col) =
                        make_float2(c[mi][nf][2], c[mi][nf][3]);
            } else {
                const float bx = __ldg(bias + col), by = __ldg(bias + col + 1);
                #pragma unroll
                for (int h = 0; h < 2; h++) {
                    const int r = r0 + 8 * h;
                    if (r >= M) continue;
                    float v0 = fmaxf(c[mi][nf][2 * h + 0] + bx, 0.f);
                    float v1 = fmaxf(c[mi][nf][2 * h + 1] + by, 0.f);
                    __nv_bfloat16 h0 = __float2bfloat16(v0);
                    __nv_bfloat16 h1 = __float2bfloat16(v1);
                    size_t o = (size_t)r * ldc + col;
                    *(__nv_bfloat162*)(Chi + o) = __nv_bfloat162(h0, h1);
                    __nv_bfloat16 l0 = __float2bfloat16(v0 - __bfloat162float(h0));
                    __nv_bfloat16 l1 = __float2bfloat16(v1 - __bfloat162float(h1));
                    *(__nv_bfloat162*)(Clo + o) = __nv_bfloat162(l0, l1);
                }
            }
        }
    }
}

// ---------------------------------------------------------------------------
// Gather aggregation (float4 lanes):
//   r = sum_e norm_e * t[src_e] + dinv[i]^2 * t[i] (+ bias) ; (relu)
//   EMIT: write bf16 hi/lo split; else fp32.
// ---------------------------------------------------------------------------
template <int D, bool RELU, bool EMIT, bool BIAS>
__global__ void agg_k(const float* __restrict__ t, float* __restrict__ outf,
                      __nv_bfloat16* __restrict__ ohi, __nv_bfloat16* __restrict__ olo,
                      const float* __restrict__ bias, int n)
{
    constexpr int L = D / 4;        // lanes per node
    constexpr int G = 256 / L;      // nodes per block
    const int lane = threadIdx.x % L;
    const int sub  = threadIdx.x / L;
    const int node = blockIdx.x * G + sub;
    if (node >= n) return;

    float4 b = make_float4(0.f, 0.f, 0.f, 0.f);
    if (BIAS) b = ((const float4*)bias)[lane];
    float di = g_dinv[node];
    float s  = di * di;
    float4 self = __ldg((const float4*)(t + (size_t)node * D) + lane);
    float4 a0 = make_float4(s * self.x + b.x, s * self.y + b.y,
                            s * self.z + b.z, s * self.w + b.w);
    float4 a1 = make_float4(0.f, 0.f, 0.f, 0.f);

    int e   = g_rowptr[node];
    int end = g_rowptr[node + 1];
    for (; e + 1 < end; e += 2) {
        int   s0 = g_csrc[e],  s1 = g_csrc[e + 1];
        float w0 = g_cnorm[e], w1 = g_cnorm[e + 1];
        float4 v0 = __ldg((const float4*)(t + (size_t)s0 * D) + lane);
        float4 v1 = __ldg((const float4*)(t + (size_t)s1 * D) + lane);
        a0.x += w0 * v0.x; a0.y += w0 * v0.y; a0.z += w0 * v0.z; a0.w += w0 * v0.w;
        a1.x += w1 * v1.x; a1.y += w1 * v1.y; a1.z += w1 * v1.z; a1.w += w1 * v1.w;
    }
    if (e < end) {
        float w0 = g_cnorm[e];
        float4 v0 = __ldg((const float4*)(t + (size_t)g_csrc[e] * D) + lane);
        a0.x += w0 * v0.x; a0.y += w0 * v0.y; a0.z += w0 * v0.z; a0.w += w0 * v0.w;
    }
    float4 r = make_float4(a0.x + a1.x, a0.y + a1.y, a0.z + a1.z, a0.w + a1.w);
    if (RELU) {
        r.x = fmaxf(r.x, 0.f); r.y = fmaxf(r.y, 0.f);
        r.z = fmaxf(r.z, 0.f); r.w = fmaxf(r.w, 0.f);
    }
    if (EMIT) {
        size_t o = (size_t)node * D + lane * 4;
        __nv_bfloat16 h0 = __float2bfloat16(r.x), h1 = __float2bfloat16(r.y);
        __nv_bfloat16 h2 = __float2bfloat16(r.z), h3 = __float2bfloat16(r.w);
        ((__nv_bfloat162*)(ohi + o))[0] = __nv_bfloat162(h0, h1);
        ((__nv_bfloat162*)(ohi + o))[1] = __nv_bfloat162(h2, h3);
        __nv_bfloat16 l0 = __float2bfloat16(r.x - __bfloat162float(h0));
        __nv_bfloat16 l1 = __float2bfloat16(r.y - __bfloat162float(h1));
        __nv_bfloat16 l2 = __float2bfloat16(r.z - __bfloat162float(h2));
        __nv_bfloat16 l3 = __float2bfloat16(r.w - __bfloat162float(h3));
        ((__nv_bfloat162*)(olo + o))[0] = __nv_bfloat162(l0, l1);
        ((__nv_bfloat162*)(olo + o))[1] = __nv_bfloat162(l2, l3);
    } else {
        ((float4*)(outf + (size_t)node * D))[lane] = r;
    }
}

// ---------------------------------------------------------------------------
// Launch
// ---------------------------------------------------------------------------
extern "C" void kernel_launch(void* const* d_in, const int* in_sizes, int n_in,
                              void* d_out, int out_size)
{
    const float* x  = (const float*)d_in[0];
    const int*   ei = (const int*)  d_in[1];
    const float* ew = (const float*)d_in[2];
    const float* W0 = (const float*)d_in[3];
    const float* b0 = (const float*)d_in[4];
    const float* W1 = (const float*)d_in[5];
    const float* b1 = (const float*)d_in[6];
    const float* W2 = (const float*)d_in[7];
    const float* b2 = (const float*)d_in[8];
    float* out = (float*)d_out;

    const int* src = ei;
    const int* dst = ei + EE;

    float *bufA;
    __nv_bfloat16 *hi, *lo, *xhi, *xlo, *w0h, *w0l, *w1h, *w1l, *w2h, *w2l;
    cudaGetSymbolAddress((void**)&bufA, g_bufA);
    cudaGetSymbolAddress((void**)&hi,  g_hi);
    cudaGetSymbolAddress((void**)&lo,  g_lo);
    cudaGetSymbolAddress((void**)&xhi, g_xhi);
    cudaGetSymbolAddress((void**)&xlo, g_xlo);
    cudaGetSymbolAddress((void**)&w0h, g_w0hi); cudaGetSymbolAddress((void**)&w0l, g_w0lo);
    cudaGetSymbolAddress((void**)&w1h, g_w1hi); cudaGetSymbolAddress((void**)&w1l, g_w1lo);
    cudaGetSymbolAddress((void**)&w2h, g_w2hi); cudaGetSymbolAddress((void**)&w2l, g_w2lo);

    const int TB = 256;
    const int gN = (NN + TB - 1) / TB;
    const int gE = (EE + TB - 1) / TB;

    // ---- normalization + coalesced CSR build ----
    k_init<<<gN, TB>>>();
    k_deg_count<<<gE, TB>>>(dst, ew);
    k_dinv<<<gN, TB>>>();
    k_blocksum<<<NBLK, 256>>>();
    k_scanblk<<<1, 512>>>();
    k_rowptr<<<NBLK, 256>>>();
    k_fill<<<gE, TB>>>(src, dst, ew);

    // ---- weight prep: transpose + split ----
    k_wsplit<<<(F_IN * HID + 255) / 256, 256>>>(W0, w0h, w0l, F_IN, HID);
    k_wsplit<<<(HID * HID + 255) / 256, 256>>>(W1, w1h, w1l, HID, HID);
    k_wsplit<<<(HID * NC + 255) / 256, 256>>>(W2, w2h, w2l, HID, NC);

    const int gridM = (NN + 127) / 128;   // 782

    // ---- Layer 0:  h0 = relu(agg(x) @ W0 + b0)   [agg first: 128-dim gathers]
    agg_k<F_IN, false, true, false><<<(NN + 7) / 8, 256>>>(
        x, nullptr, xhi, xlo, nullptr, NN);
    gemm_mma<1><<<dim3(HID / 64, gridM), 256>>>(
        NN, F_IN, xhi, xlo, w0h, w0l, nullptr, hi, lo, b0, HID);

    // ---- Layer 1:  h1 = relu(agg(h0 @ W1) + b1)
    gemm_mma<0><<<dim3(HID / 64, gridM), 256>>>(
        NN, HID, hi, lo, w1h, w1l, bufA, nullptr, nullptr, nullptr, HID);
    agg_k<HID, true, true, true><<<(NN + 3) / 4, 256>>>(
        bufA, nullptr, hi, lo, b1, NN);

    // ---- Layer 2:  out = agg(h1 @ W2) + b2   [64-dim gathers]
    gemm_mma<0><<<dim3(NC / 64, gridM), 256>>>(
        NN, HID, hi, lo, w2h, w2l, bufA, nullptr, nullptr, nullptr, NC);
    agg_k<NC, false, false, true><<<(NN + 15) / 16, 256>>>(
        bufA, out, nullptr, nullptr, b2, NN);
}